// round 8
// baseline (speedup 1.0000x reference)
#include <cuda_runtime.h>
#include <math.h>

#define NUM_Q   8
#define DIM     256
#define N_EMBED 1024
#define NROWS   65536
#define QOUT_ELEMS (NROWS * DIM)

#define TM 32       // rows per block
#define TNC 128     // codes per ct tile
#define BK 32       // k-chunk
#define NTHREADS 256
#define ATS 36      // At row stride (floats): 32 + 4 pad
#define BSROW 132   // Bs row stride (floats): 128 + 4 pad
#define NCHUNK (N_EMBED / TNC * DIM / BK)   // 64 chunks per layer pass
#define NBLK (NROWS / TM)

__device__ float g_res[NROWS * DIM];
__device__ float g_embT[NUM_Q * N_EMBED * DIM];
__device__ float g_norms[NUM_Q * N_EMBED];
__device__ float g_losspart[NUM_Q * NBLK];
__device__ int   g_counts[NUM_Q * N_EMBED];

typedef unsigned long long ull;
__device__ __forceinline__ ull fma2(ull a, ull b, ull c) {
  ull d; asm("fma.rn.f32x2 %0, %1, %2, %3;" : "=l"(d) : "l"(a), "l"(b), "l"(c));
  return d;
}
__device__ __forceinline__ ull packdup(float x) {
  ull r; asm("mov.b64 %0, {%1, %1};" : "=l"(r) : "f"(x));
  return r;
}
__device__ __forceinline__ float2 unpack2(ull v) {
  float2 f; asm("mov.b64 {%0, %1}, %2;" : "=f"(f.x), "=f"(f.y) : "l"(v));
  return f;
}

// ---------------- prep: transpose codebooks (code-major) + zero counts ----------------
__global__ void prep_kernel(const float* __restrict__ embeds) {
  int idx = blockIdx.x * 256 + threadIdx.x;
  int l = idx >> 18;
  int rem = idx & 262143;
  int d = rem >> 10;
  int k = rem & 1023;
  g_embT[((size_t)l * N_EMBED + k) * DIM + d] = embeds[idx];
  if (idx < NUM_Q * N_EMBED) g_counts[idx] = 0;
}

// ---------------- code norms: sequential d, separate mul+add ----------------
__global__ void norms_kernel(const float* __restrict__ embeds) {
  int k = blockIdx.x * 256 + threadIdx.x;
  int l = k >> 10;
  int kk = k & 1023;
  float s = 0.f;
  for (int d = 0; d < DIM; ++d) {
    float v = embeds[((size_t)l * DIM + d) * N_EMBED + kk];
    s = __fadd_rn(s, __fmul_rn(v, v));
  }
  g_norms[k] = s;
}

// ---------------- main fused VQ layer ----------------
__global__ void __launch_bounds__(NTHREADS, 3)
vq_layer_kernel(const float* __restrict__ x,
                const float* __restrict__ embeds,
                float* __restrict__ qout,
                int layer) {
  extern __shared__ float sm[];
  float* At    = sm;                           // [DIM][ATS] transposed residual
  float* Bs    = At + DIM * ATS;               // [2][BK][BSROW] double-buffered
  float* sRN   = Bs + 2 * BK * BSROW;          // [TM]
  int*   sInd  = (int*)(sRN + TM);             // [TM]
  float* sRed  = (float*)(sInd + TM);          // [8]
  float* sArgV = sRed + 8;                     // [8][TM]
  int*   sArgI = (int*)(sArgV + 8 * TM);       // [8][TM]

  const int tid = threadIdx.x;
  const int wid = tid >> 5, lane = tid & 31;
  const int rg = lane & 15;             // row group (2 rows)
  const int cg = lane >> 4;             // code group (8 codes) within eighth
  const int rowsel  = rg * 2;
  const int codesel = wid * 16 + cg * 8;     // tile-local first code

  const float* resin = (layer == 0) ? x : g_res;
  const float* rbase = resin + (size_t)blockIdx.x * TM * DIM;

  // ---- ||r||^2 per row (XLA row-reduce pattern, from global; bit pattern per row) ----
  #pragma unroll 1
  for (int rr = 0; rr < 4; ++rr) {
    int row = wid * 4 + rr;
    const float* rp = rbase + row * DIM;
    float p0 = 0.f, p1 = 0.f;
    #pragma unroll
    for (int i = 0; i < 4; ++i) {
      float2 v = __ldg((const float2*)&rp[i * 64 + 2 * lane]);
      p0 = __fadd_rn(p0, __fmul_rn(v.x, v.x));
      p1 = __fadd_rn(p1, __fmul_rn(v.y, v.y));
    }
    float a = __fadd_rn(p0, p1);
    #pragma unroll
    for (int off = 16; off > 0; off >>= 1)
      a = __fadd_rn(a, __shfl_down_sync(0xffffffff, a, off));
    if (lane == 0) sRN[row] = a;
  }

  // ---- scatter-store transposed residual: At[d][row] ----
  {
    const int row = tid & 31;     // = lane
    const int g0  = tid >> 5;     // = wid (0..7)
    const float* rp = rbase + row * DIM;
    #pragma unroll
    for (int g = 0; g < 8; ++g) {
      int gg = g0 + g * 8;
      float4 v = __ldg((const float4*)rp + gg);
      At[(gg * 4 + 0) * ATS + row] = v.x;
      At[(gg * 4 + 1) * ATS + row] = v.y;
      At[(gg * 4 + 2) * ATS + row] = v.z;
      At[(gg * 4 + 3) * ATS + row] = v.w;
    }
  }

  // B-fill assignment: thread loads 16 consecutive floats of one k-row
  const int brow = tid >> 3;          // 0..31
  const int bcol = (tid & 7) * 16;    // 0..112

  auto bsrc = [&](int idx) {
    int ict = idx >> 3, ikc = idx & 7;
    return embeds + ((size_t)(layer * DIM + ikc * BK + brow)) * N_EMBED
           + ict * TNC + bcol;
  };

  // prologue: chunk0 -> buf0 directly; LDG chunk1 into regs
  float4 nv0, nv1, nv2, nv3;
  {
    const float* g = bsrc(0);
    float4 v0 = __ldg((const float4*)g);
    float4 v1 = __ldg((const float4*)g + 1);
    float4 v2 = __ldg((const float4*)g + 2);
    float4 v3 = __ldg((const float4*)g + 3);
    float* bd = Bs + brow * BSROW + bcol;
    *(float4*)(bd + 0)  = v0;
    *(float4*)(bd + 4)  = v1;
    *(float4*)(bd + 8)  = v2;
    *(float4*)(bd + 12) = v3;
    const float* g1 = bsrc(1);
    nv0 = __ldg((const float4*)g1);
    nv1 = __ldg((const float4*)g1 + 1);
    nv2 = __ldg((const float4*)g1 + 2);
    nv3 = __ldg((const float4*)g1 + 3);
  }
  __syncthreads();

  float bestv[2];
  int   besti[2];
  #pragma unroll
  for (int i = 0; i < 2; ++i) { bestv[i] = 3.4028235e38f; besti[i] = 0; }

  for (int ct = 0; ct < N_EMBED / TNC; ++ct) {
    ull acc[2][4];   // [row r][code pair jp]
    #pragma unroll
    for (int r = 0; r < 2; ++r)
      #pragma unroll
      for (int j = 0; j < 4; ++j) acc[r][j] = 0ull;

    for (int kc = 0; kc < DIM / BK; ++kc) {
      const int idx = ct * 8 + kc;
      const int p = idx & 1;

      // store prefetched chunk idx+1 into the other buffer
      if (idx + 1 < NCHUNK) {
        float* bd = Bs + (p ^ 1) * (BK * BSROW) + brow * BSROW + bcol;
        *(float4*)(bd + 0)  = nv0;
        *(float4*)(bd + 4)  = nv1;
        *(float4*)(bd + 8)  = nv2;
        *(float4*)(bd + 12) = nv3;
      }
      // LDG chunk idx+2
      if (idx + 2 < NCHUNK) {
        const float* g = bsrc(idx + 2);
        nv0 = __ldg((const float4*)g);
        nv1 = __ldg((const float4*)g + 1);
        nv2 = __ldg((const float4*)g + 2);
        nv3 = __ldg((const float4*)g + 3);
      }

      // compute on buffer p, software-pipelined LDS
      const float* apd = At + (kc * BK) * ATS + rowsel;
      const float* bpd = Bs + p * (BK * BSROW) + codesel;
      float2 a_c = *(const float2*)apd;
      ulonglong2 b01_c = *(const ulonglong2*)bpd;
      ulonglong2 b23_c = *(const ulonglong2*)(bpd + 4);
      #pragma unroll
      for (int d = 0; d < BK; ++d) {
        float2 a_n;
        ulonglong2 b01_n, b23_n;
        if (d + 1 < BK) {
          a_n   = *(const float2*)(apd + (d + 1) * ATS);
          b01_n = *(const ulonglong2*)(bpd + (d + 1) * BSROW);
          b23_n = *(const ulonglong2*)(bpd + (d + 1) * BSROW + 4);
        }
        ull ad0 = packdup(a_c.x), ad1 = packdup(a_c.y);
        acc[0][0] = fma2(ad0, b01_c.x, acc[0][0]);
        acc[0][1] = fma2(ad0, b01_c.y, acc[0][1]);
        acc[0][2] = fma2(ad0, b23_c.x, acc[0][2]);
        acc[0][3] = fma2(ad0, b23_c.y, acc[0][3]);
        acc[1][0] = fma2(ad1, b01_c.x, acc[1][0]);
        acc[1][1] = fma2(ad1, b01_c.y, acc[1][1]);
        acc[1][2] = fma2(ad1, b23_c.x, acc[1][2]);
        acc[1][3] = fma2(ad1, b23_c.y, acc[1][3]);
        a_c = a_n; b01_c = b01_n; b23_c = b23_n;
      }
      __syncthreads();   // one barrier per chunk
    }

    // dist = (rn - 2*ab) + en, exact association, ascending code order
    const int cbase = ct * TNC + codesel;
    #pragma unroll
    for (int r = 0; r < 2; ++r) {
      float rn = sRN[rowsel + r];
      #pragma unroll
      for (int jp = 0; jp < 4; ++jp) {
        float2 s = unpack2(acc[r][jp]);
        int code0 = cbase + jp * 2;
        float en0 = __ldg(&g_norms[layer * N_EMBED + code0]);
        float en1 = __ldg(&g_norms[layer * N_EMBED + code0 + 1]);
        float d0 = __fadd_rn(__fadd_rn(rn, __fmul_rn(-2.0f, s.x)), en0);
        float d1 = __fadd_rn(__fadd_rn(rn, __fmul_rn(-2.0f, s.y)), en1);
        if (d0 < bestv[r]) { bestv[r] = d0; besti[r] = code0; }
        if (d1 < bestv[r]) { bestv[r] = d1; besti[r] = code0 + 1; }
      }
    }
  }

  // in-warp argmin reduce across the 2 code-groups (lanes xor 16)
  #pragma unroll
  for (int r = 0; r < 2; ++r) {
    float ov = __shfl_xor_sync(0xffffffff, bestv[r], 16);
    int   oi = __shfl_xor_sync(0xffffffff, besti[r], 16);
    if (ov < bestv[r] || (ov == bestv[r] && oi < besti[r])) {
      bestv[r] = ov; besti[r] = oi;
    }
  }
  if (cg == 0) {
    #pragma unroll
    for (int r = 0; r < 2; ++r) {
      sArgV[wid * TM + rowsel + r] = bestv[r];
      sArgI[wid * TM + rowsel + r] = besti[r];
    }
  }
  __syncthreads();

  // cross-warp argmin over the 8 code eighths (ascending code order)
  if (tid < TM) {
    float bv = sArgV[tid];
    int   bi = sArgI[tid];
    #pragma unroll
    for (int q = 1; q < 8; ++q) {
      float v = sArgV[q * TM + tid];
      int   i = sArgI[q * TM + tid];
      if (v < bv || (v == bv && i < bi)) { bv = v; bi = i; }
    }
    sInd[tid] = bi;
  }
  __syncthreads();

  // ------------- epilogue: exact straight-through chain -------------
  float lsum = 0.f;
  const size_t rowbase = (size_t)blockIdx.x * TM;

  #pragma unroll 1
  for (int rr = 0; rr < 4; ++rr) {
    int r = wid * 4 + rr;
    int c = sInd[r];
    const float* q   = g_embT + ((size_t)layer * N_EMBED + c) * DIM;
    float* outp      = qout  + (rowbase + r) * DIM;
    float* resp      = g_res + (rowbase + r) * DIM;
    const float* rsm = rbase + r * DIM;
    #pragma unroll
    for (int h = 0; h < 2; ++h) {
      int d = lane * 4 + h * 128;
      float4 qv = __ldg((const float4*)(q + d));
      float4 rv = __ldg((const float4*)(rsm + d));
      float4 dq, qst, nr;
      dq.x = __fadd_rn(qv.x, -rv.x); dq.y = __fadd_rn(qv.y, -rv.y);
      dq.z = __fadd_rn(qv.z, -rv.z); dq.w = __fadd_rn(qv.w, -rv.w);
      qst.x = __fadd_rn(rv.x, dq.x); qst.y = __fadd_rn(rv.y, dq.y);
      qst.z = __fadd_rn(rv.z, dq.z); qst.w = __fadd_rn(rv.w, dq.w);
      nr.x = __fadd_rn(rv.x, -qst.x); nr.y = __fadd_rn(rv.y, -qst.y);
      nr.z = __fadd_rn(rv.z, -qst.z); nr.w = __fadd_rn(rv.w, -qst.w);
      *(float4*)(resp + d) = nr;
      float4 ov;
      if (layer == 0) {
        ov = qst;
      } else {
        ov = *(const float4*)(outp + d);
        ov.x = __fadd_rn(ov.x, qst.x); ov.y = __fadd_rn(ov.y, qst.y);
        ov.z = __fadd_rn(ov.z, qst.z); ov.w = __fadd_rn(ov.w, qst.w);
      }
      *(float4*)(outp + d) = ov;
      lsum += __fmul_rn(dq.x, dq.x) + __fmul_rn(dq.y, dq.y)
            + __fmul_rn(dq.z, dq.z) + __fmul_rn(dq.w, dq.w);
    }
    if (lane == 0) atomicAdd(&g_counts[layer * N_EMBED + c], 1);
  }

  #pragma unroll
  for (int off = 16; off > 0; off >>= 1)
    lsum += __shfl_xor_sync(0xffffffff, lsum, off);
  if (lane == 0) sRed[wid] = lsum;
  __syncthreads();
  if (tid == 0) {
    float s = 0.f;
    #pragma unroll
    for (int w = 0; w < 8; ++w) s += sRed[w];
    g_losspart[layer * NBLK + blockIdx.x] = s;
  }
}

// ---------------- finalize: loss mean + perplexity ----------------
__global__ void finalize_kernel(float* __restrict__ out) {
  const int l = blockIdx.x;
  const int tid = threadIdx.x;
  __shared__ double sd[256];
  __shared__ float  sf[256];
  double ls = 0.0;
  float  es = 0.f;
  for (int i = tid; i < NBLK; i += 256)
    ls += (double)g_losspart[l * NBLK + i];
  for (int i = tid; i < N_EMBED; i += 256) {
    float p = (float)g_counts[l * N_EMBED + i] * (1.0f / (float)NROWS);
    es += p * logf(__fadd_rn(p, 1e-10f));
  }
  sd[tid] = ls; sf[tid] = es;
  __syncthreads();
  for (int s = 128; s > 0; s >>= 1) {
    if (tid < s) { sd[tid] += sd[tid + s]; sf[tid] += sf[tid + s]; }
    __syncthreads();
  }
  if (tid == 0) {
    out[QOUT_ELEMS + l]         = (float)(sd[0] / (double)QOUT_ELEMS);
    out[QOUT_ELEMS + NUM_Q + l] = expf(-sf[0]);
  }
}

extern "C" void kernel_launch(void* const* d_in, const int* in_sizes, int n_in,
                              void* d_out, int out_size) {
  const float* x      = (const float*)d_in[0];
  const float* embeds = (const float*)d_in[1];
  float* out          = (float*)d_out;

  const int smem_bytes =
      (DIM * ATS + 2 * BK * BSROW + TM + TM + 8 + 8 * TM + 8 * TM) * 4;
  cudaFuncSetAttribute(vq_layer_kernel,
                       cudaFuncAttributeMaxDynamicSharedMemorySize, smem_bytes);

  prep_kernel<<<(NUM_Q * N_EMBED * DIM) / 256, 256>>>(embeds);
  norms_kernel<<<(NUM_Q * N_EMBED) / 256, 256>>>(embeds);

  for (int l = 0; l < NUM_Q; ++l) {
    vq_layer_kernel<<<NBLK, NTHREADS, smem_bytes>>>(x, embeds, out, l);
  }
  finalize_kernel<<<NUM_Q, 256>>>(out);
}

// round 10
// speedup vs baseline: 1.6432x; 1.6432x over previous
#include <cuda_runtime.h>
#include <cuda_bf16.h>
#include <math.h>
#include <stdint.h>

#define NUM_Q   8
#define DIM     256
#define N_EMBED 1024
#define NROWS   65536
#define QOUT_ELEMS (NROWS * DIM)

#define MCTA   128
#define KTOT   768
#define KCH    64
#define NKC    12                  // k-chunks per n-tile
#define NNT    8                   // n-tiles of 128 codes
#define NCH    (NNT * NKC)         // 96 chunks
#define NBLK   (NROWS / MCTA)      // 512
#define THREADS 256
#define TAU    0.05f
#define NC     4

// smem layout (bytes)
#define BUF_SZ   32768             // A(16KB)+B(16KB) per chunk buffer
#define OFF_EN   (4 * BUF_SZ)      // 131072: 1024 floats
#define OFF_RN   (OFF_EN + 4096)
#define OFF_IND  (OFF_RN + 512)
#define OFF_RED  (OFF_IND + 512)
#define OFF_CV   (OFF_RED + 128)
#define OFF_CI   (OFF_CV + 16384)
#define SMEM_TOTAL (OFF_CI + 16384)   // 169088

__device__ float g_res[NROWS * DIM];
__device__ float g_embT[NUM_Q * N_EMBED * DIM];
__device__ float g_norms[NUM_Q * N_EMBED];
__device__ float g_losspart[NUM_Q * NBLK];
__device__ int   g_counts[NUM_Q * N_EMBED];
__device__ __nv_bfloat16 g_Abf[(size_t)NROWS * KTOT];
__device__ __nv_bfloat16 g_Bbf[(size_t)NUM_Q * N_EMBED * KTOT];

__device__ __forceinline__ uint32_t smem_u32(const void* p) {
  uint32_t a;
  asm("{ .reg .u64 t; cvta.to.shared.u64 t, %1; cvt.u32.u64 %0, t; }"
      : "=r"(a) : "l"(p));
  return a;
}
__device__ __forceinline__ void cp16(uint32_t dst, const void* src) {
  asm volatile("cp.async.cg.shared.global [%0], [%1], 16;"
               :: "r"(dst), "l"(src) : "memory");
}
__device__ __forceinline__ void cp_commit() {
  asm volatile("cp.async.commit_group;" ::: "memory");
}
__device__ __forceinline__ void mma_bf16(float* d, const uint32_t* a,
                                         uint32_t b0, uint32_t b1) {
  asm volatile(
      "mma.sync.aligned.m16n8k16.row.col.f32.bf16.bf16.f32 "
      "{%0,%1,%2,%3}, {%4,%5,%6,%7}, {%8,%9}, {%0,%1,%2,%3};"
      : "+f"(d[0]), "+f"(d[1]), "+f"(d[2]), "+f"(d[3])
      : "r"(a[0]), "r"(a[1]), "r"(a[2]), "r"(a[3]), "r"(b0), "r"(b1));
}
__device__ __forceinline__ void ins4(float v, int c, float* cv, int* ci) {
  if (v < cv[NC - 1]) {
    float pv = v; int pc = c;
    #pragma unroll
    for (int q = 0; q < NC; ++q) {
      if (pv < cv[q]) {
        float tv = cv[q]; int tc = ci[q];
        cv[q] = pv; ci[q] = pc; pv = tv; pc = tc;
      }
    }
  }
}

// ---------------- prep: embT transpose + counts zero + B bf16 split ----------------
__global__ void prep_kernel(const float* __restrict__ embeds) {
  int idx = blockIdx.x * 256 + threadIdx.x;   // over [l][d][k]
  int l = idx >> 18;
  int rem = idx & 262143;
  int d = rem >> 10;
  int k = rem & 1023;
  float v = embeds[idx];
  g_embT[((size_t)l * N_EMBED + k) * DIM + d] = v;
  __nv_bfloat16 hi = __float2bfloat16(v);
  __nv_bfloat16 lo = __float2bfloat16(__fsub_rn(v, __bfloat162float(hi)));
  __nv_bfloat16* b = g_Bbf + ((size_t)l * N_EMBED + k) * KTOT;
  b[d] = hi; b[256 + d] = lo; b[512 + d] = hi;   // B = [e_hi | e_lo | e_hi]
  if (idx < NUM_Q * N_EMBED) g_counts[idx] = 0;
}

// ---------------- code norms: sequential d, separate mul+add ----------------
__global__ void norms_kernel(const float* __restrict__ embeds) {
  int k = blockIdx.x * 256 + threadIdx.x;
  int l = k >> 10;
  int kk = k & 1023;
  float s = 0.f;
  for (int d = 0; d < DIM; ++d) {
    float v = embeds[((size_t)l * DIM + d) * N_EMBED + kk];
    s = __fadd_rn(s, __fmul_rn(v, v));
  }
  g_norms[k] = s;
}

// ---------------- layer-0 A bf16 split: A = [r_hi | r_hi | r_lo] ----------------
__global__ void convertA_kernel(const float* __restrict__ x) {
  size_t idx = (size_t)blockIdx.x * 256 + threadIdx.x;
  float v = x[idx];
  int row = (int)(idx >> 8);
  int d = (int)(idx & 255);
  __nv_bfloat16 hi = __float2bfloat16(v);
  __nv_bfloat16 lo = __float2bfloat16(__fsub_rn(v, __bfloat162float(hi)));
  __nv_bfloat16* a = g_Abf + (size_t)row * KTOT;
  a[d] = hi; a[256 + d] = hi; a[512 + d] = lo;
}

// ---------------- main fused VQ layer: mma.sync bf16 + exact rescore ----------------
__global__ void __launch_bounds__(THREADS)
vq_mma_kernel(const float* __restrict__ x,
              float* __restrict__ qout,
              int layer) {
  extern __shared__ char sm[];
  const uint32_t sbase = smem_u32(sm);
  float* sEN  = (float*)(sm + OFF_EN);
  float* sRN  = (float*)(sm + OFF_RN);
  int*   sInd = (int*)(sm + OFF_IND);
  float* sRed = (float*)(sm + OFF_RED);
  float* sCV  = (float*)(sm + OFF_CV);
  int*   sCI  = (int*)(sm + OFF_CI);

  const int tid = threadIdx.x, wid = tid >> 5, lane = tid & 31;
  const int mw = wid & 3;          // m-warp: rows mw*32..+31
  const int nw = wid >> 2;         // n-warp: codes nw*64..+63 within tile
  const int lr = lane >> 2;        // 0..7
  const int lc = lane & 3;         // 0..3

  const float* resin = (layer == 0) ? x : g_res;
  const float* rbase = resin + (size_t)blockIdx.x * MCTA * DIM;
  const __nv_bfloat16* Ag = g_Abf + (size_t)blockIdx.x * MCTA * KTOT;
  const __nv_bfloat16* Bg = g_Bbf + (size_t)layer * N_EMBED * KTOT;

  // code norms into smem
  for (int i = tid; i < N_EMBED; i += THREADS)
    sEN[i] = g_norms[layer * N_EMBED + i];

  // ---- ||r||^2 per row (XLA row-reduce pattern; 16 rows per warp) ----
  #pragma unroll 1
  for (int rr = 0; rr < 16; ++rr) {
    int row = wid * 16 + rr;
    const float* rp = rbase + row * DIM;
    float p0 = 0.f, p1 = 0.f;
    #pragma unroll
    for (int i = 0; i < 4; ++i) {
      float2 v = __ldg((const float2*)&rp[i * 64 + 2 * lane]);
      p0 = __fadd_rn(p0, __fmul_rn(v.x, v.x));
      p1 = __fadd_rn(p1, __fmul_rn(v.y, v.y));
    }
    float a = __fadd_rn(p0, p1);
    #pragma unroll
    for (int off = 16; off > 0; off >>= 1)
      a = __fadd_rn(a, __shfl_down_sync(0xffffffff, a, off));
    if (lane == 0) sRN[row] = a;
  }

  // chunk fill via cp.async (16B granules, XOR swizzle keeps 16B blocks intact)
  auto fill = [&](int ch) {
    const int nt = ch / NKC, kc = ch - nt * NKC;
    const uint32_t base = sbase + (uint32_t)(ch & 3) * BUF_SZ;
    #pragma unroll
    for (int t = 0; t < 4; ++t) {
      int idx = tid + t * 256;          // 0..1023
      int row = idx >> 3, seg = idx & 7;
      uint32_t dw = (uint32_t)(row * 32 + ((seg * 4) ^ ((row & 7) * 4)));
      cp16(base + dw * 4, Ag + (size_t)row * KTOT + kc * KCH + seg * 8);
      cp16(base + 16384 + dw * 4,
           Bg + (size_t)(nt * 128 + row) * KTOT + kc * KCH + seg * 8);
    }
    cp_commit();
  };

  fill(0); fill(1); fill(2);

  float acc[2][8][4];
  float cv[4][NC]; int ci[4][NC];
  #pragma unroll
  for (int li = 0; li < 4; ++li)
    #pragma unroll
    for (int q = 0; q < NC; ++q) { cv[li][q] = 3.4028235e38f; ci[li][q] = 0; }

  for (int c = 0; c < NCH; ++c) {
    const int nt = c / NKC, kc = c - nt * NKC;

    if (c <= NCH - 3)      asm volatile("cp.async.wait_group 2;" ::: "memory");
    else if (c == NCH - 2) asm volatile("cp.async.wait_group 1;" ::: "memory");
    else                   asm volatile("cp.async.wait_group 0;" ::: "memory");
    __syncthreads();

    if (kc == 0) {
      #pragma unroll
      for (int i = 0; i < 2; ++i)
        #pragma unroll
        for (int j = 0; j < 8; ++j)
          #pragma unroll
          for (int q = 0; q < 4; ++q) acc[i][j][q] = 0.f;
    }

    const uint32_t* AW = (const uint32_t*)(sm + (size_t)(c & 3) * BUF_SZ);
    const uint32_t* BW = AW + 4096;
    #pragma unroll
    for (int ks = 0; ks < 4; ++ks) {
      const int w0 = ks * 8 + lc;
      const int sw  = w0 ^ (lr << 2);
      const int sw4 = (w0 + 4) ^ (lr << 2);
      uint32_t a0[4], a1[4];
      {
        const int r0 = mw * 32 + lr;
        a0[0] = AW[(r0)      * 32 + sw];
        a0[1] = AW[(r0 + 8)  * 32 + sw];
        a0[2] = AW[(r0)      * 32 + sw4];
        a0[3] = AW[(r0 + 8)  * 32 + sw4];
        a1[0] = AW[(r0 + 16) * 32 + sw];
        a1[1] = AW[(r0 + 24) * 32 + sw];
        a1[2] = AW[(r0 + 16) * 32 + sw4];
        a1[3] = AW[(r0 + 24) * 32 + sw4];
      }
      #pragma unroll
      for (int j = 0; j < 8; ++j) {
        const int n0 = nw * 64 + j * 8 + lr;
        uint32_t b0 = BW[n0 * 32 + sw];
        uint32_t b1 = BW[n0 * 32 + sw4];
        mma_bf16(acc[0][j], a0, b0, b1);
        mma_bf16(acc[1][j], a1, b0, b1);
      }
    }

    if (kc == NKC - 1) {
      const int C00 = nt * 128 + nw * 64 + lc * 2;
      #pragma unroll
      for (int i = 0; i < 2; ++i) {
        #pragma unroll
        for (int j = 0; j < 8; ++j) {
          int code0 = C00 + j * 8;
          float e0 = sEN[code0], e1 = sEN[code0 + 1];
          ins4(__fmaf_rn(-2.f, acc[i][j][0], e0), code0,     cv[i * 2],     ci[i * 2]);
          ins4(__fmaf_rn(-2.f, acc[i][j][1], e1), code0 + 1, cv[i * 2],     ci[i * 2]);
          ins4(__fmaf_rn(-2.f, acc[i][j][2], e0), code0,     cv[i * 2 + 1], ci[i * 2 + 1]);
          ins4(__fmaf_rn(-2.f, acc[i][j][3], e1), code0 + 1, cv[i * 2 + 1], ci[i * 2 + 1]);
        }
      }
    }

    if (c + 3 < NCH) fill(c + 3);
  }

  // dump candidates: row r has 32 slots (2 nw x 4 lc x 4)
  {
    const int slot = nw * 16 + lc * 4;
    #pragma unroll
    for (int i = 0; i < 2; ++i)
      #pragma unroll
      for (int a = 0; a < 2; ++a) {
        int r = mw * 32 + i * 16 + a * 8 + lr;
        int li = i * 2 + a;
        #pragma unroll
        for (int q = 0; q < NC; ++q) {
          sCV[r * 32 + slot + q] = cv[li][q];
          sCI[r * 32 + slot + q] = ci[li][q];
        }
      }
  }
  __syncthreads();

  // ---- exact rescore (bit-identical reference chain) ----
  if (tid < MCTA) {
    const int r = tid;
    float vmin = 3.4028235e38f;
    #pragma unroll 4
    for (int s = 0; s < 32; ++s) vmin = fminf(vmin, sCV[r * 32 + s]);
    const float thr = vmin + TAU;
    const float rn = sRN[r];
    const float* rp = rbase + r * DIM;
    float bestd = 3.4028235e38f;
    int   bestc = 0x7fffffff;
    #pragma unroll 1
    for (int s = 0; s < 32; ++s) {
      if (sCV[r * 32 + s] <= thr) {
        int code = sCI[r * 32 + s];
        const float* ep = g_embT + ((size_t)layer * N_EMBED + code) * DIM;
        float ab = 0.f;
        #pragma unroll 8
        for (int d4 = 0; d4 < 64; ++d4) {
          float4 rv = __ldg((const float4*)rp + d4);
          float4 ev = __ldg((const float4*)ep + d4);
          ab = __fmaf_rn(rv.x, ev.x, ab);
          ab = __fmaf_rn(rv.y, ev.y, ab);
          ab = __fmaf_rn(rv.z, ev.z, ab);
          ab = __fmaf_rn(rv.w, ev.w, ab);
        }
        float en = sEN[code];
        float dist = __fadd_rn(__fadd_rn(rn, __fmul_rn(-2.0f, ab)), en);
        if (dist < bestd || (dist == bestd && code < bestc)) {
          bestd = dist; bestc = code;
        }
      }
    }
    sInd[r] = bestc;
  }
  __syncthreads();

  // ---- straight-through epilogue (exact chain) + fused next-layer A split ----
  float lsum = 0.f;
  const size_t rowbase = (size_t)blockIdx.x * MCTA;
  #pragma unroll 1
  for (int rr = 0; rr < 16; ++rr) {
    int r = wid * 16 + rr;
    int cc = sInd[r];
    const float* q   = g_embT + ((size_t)layer * N_EMBED + cc) * DIM;
    float* outp      = qout  + (rowbase + r) * DIM;
    float* resp      = g_res + (rowbase + r) * DIM;
    const float* rsm = rbase + r * DIM;
    __nv_bfloat16* arow = g_Abf + (rowbase + r) * KTOT;
    #pragma unroll
    for (int h = 0; h < 2; ++h) {
      int d = lane * 4 + h * 128;
      float4 qv = __ldg((const float4*)(q + d));
      float4 rv = __ldg((const float4*)(rsm + d));
      float4 dq, qst, nr;
      dq.x = __fadd_rn(qv.x, -rv.x); dq.y = __fadd_rn(qv.y, -rv.y);
      dq.z = __fadd_rn(qv.z, -rv.z); dq.w = __fadd_rn(qv.w, -rv.w);
      qst.x = __fadd_rn(rv.x, dq.x); qst.y = __fadd_rn(rv.y, dq.y);
      qst.z = __fadd_rn(rv.z, dq.z); qst.w = __fadd_rn(rv.w, dq.w);
      nr.x = __fadd_rn(rv.x, -qst.x); nr.y = __fadd_rn(rv.y, -qst.y);
      nr.z = __fadd_rn(rv.z, -qst.z); nr.w = __fadd_rn(rv.w, -qst.w);
      *(float4*)(resp + d) = nr;
      float4 ov;
      if (layer == 0) {
        ov = qst;
      } else {
        ov = *(const float4*)(outp + d);
        ov.x = __fadd_rn(ov.x, qst.x); ov.y = __fadd_rn(ov.y, qst.y);
        ov.z = __fadd_rn(ov.z, qst.z); ov.w = __fadd_rn(ov.w, qst.w);
      }
      *(float4*)(outp + d) = ov;
      lsum += __fmul_rn(dq.x, dq.x) + __fmul_rn(dq.y, dq.y)
            + __fmul_rn(dq.z, dq.z) + __fmul_rn(dq.w, dq.w);
      if (layer < NUM_Q - 1) {
        __nv_bfloat16 hx = __float2bfloat16(nr.x);
        __nv_bfloat16 hy = __float2bfloat16(nr.y);
        __nv_bfloat16 hz = __float2bfloat16(nr.z);
        __nv_bfloat16 hw = __float2bfloat16(nr.w);
        __nv_bfloat16 lx = __float2bfloat16(__fsub_rn(nr.x, __bfloat162float(hx)));
        __nv_bfloat16 ly = __float2bfloat16(__fsub_rn(nr.y, __bfloat162float(hy)));
        __nv_bfloat16 lz = __float2bfloat16(__fsub_rn(nr.z, __bfloat162float(hz)));
        __nv_bfloat16 lw = __float2bfloat16(__fsub_rn(nr.w, __bfloat162float(hw)));
        __nv_bfloat162 h01, h23, l01, l23;
        h01.x = hx; h01.y = hy; h23.x = hz; h23.y = hw;
        l01.x = lx; l01.y = ly; l23.x = lz; l23.y = lw;
        uint2 hv, lv;
        hv.x = *(uint32_t*)&h01; hv.y = *(uint32_t*)&h23;
        lv.x = *(uint32_t*)&l01; lv.y = *(uint32_t*)&l23;
        *(uint2*)(arow + d)       = hv;
        *(uint2*)(arow + 256 + d) = hv;
        *(uint2*)(arow + 512 + d) = lv;
      }
    }
    if (lane == 0) atomicAdd(&g_counts[layer * N_EMBED + cc], 1);
  }
  #pragma unroll
  for (int off = 16; off > 0; off >>= 1)
    lsum += __shfl_xor_sync(0xffffffff, lsum, off);
  if (lane == 0) sRed[wid] = lsum;
  __syncthreads();
  if (tid == 0) {
    float s = 0.f;
    #pragma unroll
    for (int w = 0; w < 8; ++w) s += sRed[w];
    g_losspart[layer * NBLK + blockIdx.x] = s;
  }
}

// ---------------- finalize: loss mean + perplexity ----------------
__global__ void finalize_kernel(float* __restrict__ out) {
  const int l = blockIdx.x;
  const int tid = threadIdx.x;
  __shared__ double sd[256];
  __shared__ float  sf[256];
  double ls = 0.0;
  float  es = 0.f;
  for (int i = tid; i < NBLK; i += 256)
    ls += (double)g_losspart[l * NBLK + i];
  for (int i = tid; i < N_EMBED; i += 256) {
    float p = (float)g_counts[l * N_EMBED + i] * (1.0f / (float)NROWS);
    es += p * logf(__fadd_rn(p, 1e-10f));
  }
  sd[tid] = ls; sf[tid] = es;
  __syncthreads();
  for (int s = 128; s > 0; s >>= 1) {
    if (tid < s) { sd[tid] += sd[tid + s]; sf[tid] += sf[tid + s]; }
    __syncthreads();
  }
  if (tid == 0) {
    out[QOUT_ELEMS + l]         = (float)(sd[0] / (double)QOUT_ELEMS);
    out[QOUT_ELEMS + NUM_Q + l] = expf(-sf[0]);
  }
}

extern "C" void kernel_launch(void* const* d_in, const int* in_sizes, int n_in,
                              void* d_out, int out_size) {
  const float* x      = (const float*)d_in[0];
  const float* embeds = (const float*)d_in[1];
  float* out          = (float*)d_out;

  cudaFuncSetAttribute(vq_mma_kernel,
                       cudaFuncAttributeMaxDynamicSharedMemorySize, SMEM_TOTAL);

  prep_kernel<<<(NUM_Q * N_EMBED * DIM) / 256, 256>>>(embeds);
  norms_kernel<<<(NUM_Q * N_EMBED) / 256, 256>>>(embeds);
  convertA_kernel<<<(NROWS * DIM) / 256, 256>>>(x);

  for (int l = 0; l < NUM_Q; ++l) {
    vq_mma_kernel<<<NBLK, THREADS, SMEM_TOTAL>>>(x, out, l);
  }
  finalize_kernel<<<NUM_Q, 256>>>(out);
}